// round 2
// baseline (speedup 1.0000x reference)
#include <cuda_runtime.h>
#include <cuda_bf16.h>
#include <math.h>

#define NN 12000
#define EE 384000
#define FIN 512
#define FHID 256
#define FOUT 64

// ---------------- scratch (static __device__, no allocs) ----------------
__device__ int   g_is64;
__device__ float g_deg[NN];
__device__ float g_dinv[NN];
__device__ int   g_rowptr[NN + 1];
__device__ int   g_fill[NN];
__device__ int   g_src[EE];
__device__ float g_w[EE];
__device__ float g_hw[NN * FHID];   // linear output buffer (reused per layer)
__device__ float g_h[NN * FHID];    // conv output buffer (reused per layer)
__device__ float g_z[NN * FOUT];    // mu
__device__ float g_zT[FOUT * NN];   // mu transposed (for decoder B tiles)

// ---------------- small helpers ----------------
__device__ __forceinline__ unsigned long long pk2(float x, float y) {
    unsigned long long r;
    asm("mov.b64 %0, {%1, %2};" : "=l"(r) : "f"(x), "f"(y));
    return r;
}
__device__ __forceinline__ void ffma2(unsigned long long& c,
                                      unsigned long long a,
                                      unsigned long long b) {
    asm("fma.rn.f32x2 %0, %1, %2, %0;" : "+l"(c) : "l"(a), "l"(b));
}
__device__ __forceinline__ float2 upk2(unsigned long long v) {
    float2 r;
    asm("mov.b64 {%0, %1}, %2;" : "=f"(r.x), "=f"(r.y) : "l"(v));
    return r;
}
__device__ __forceinline__ float fsig(float s) {
    return __fdividef(1.0f, 1.0f + __expf(-s));
}

// Load edge index element `idx` (0..2*EE-1) honoring the detected dtype,
// clamped to [0, NN) so a surprise dtype can never cause an OOB access.
__device__ __forceinline__ int load_ei(const void* ei, long long idx) {
    int v;
    if (g_is64) v = (int)((const long long*)ei)[idx];
    else        v = ((const int*)ei)[idx];
    return min(max(v, 0), NN - 1);
}

// ---------------- dtype detection + preprocessing ----------------
__global__ void detect_kernel(const void* ei) {
    // int64 little-endian with all values < 2^31  =>  odd int32 words are 0
    const int* w = (const int*)ei;
    bool is64 = true;
    for (int i = 1; i < 64; i += 2)
        if (w[i] != 0) { is64 = false; break; }
    g_is64 = is64 ? 1 : 0;
}

__global__ void init_kernel() {
    int i = blockIdx.x * blockDim.x + threadIdx.x;
    if (i < NN) { g_deg[i] = 1.0f; g_fill[i] = 0; }  // 1.0 = self loop
}

__global__ void count_kernel(const void* __restrict__ ei) {
    int e = blockIdx.x * blockDim.x + threadIdx.x;
    if (e < EE) atomicAdd(&g_deg[load_ei(ei, (long long)EE + e)], 1.0f);
}

__global__ void dinv_kernel() {
    int i = blockIdx.x * blockDim.x + threadIdx.x;
    if (i < NN) g_dinv[i] = rsqrtf(g_deg[i]);
}

__global__ void scan_kernel() {
    __shared__ int sh[1024];
    __shared__ int s_off;
    int tid = threadIdx.x;
    if (tid == 0) s_off = 0;
    __syncthreads();
    for (int base = 0; base < NN; base += 1024) {
        int i = base + tid;
        int v = (i < NN) ? ((int)(g_deg[i] + 0.5f) - 1) : 0;  // in-degree (no self loop)
        sh[tid] = v;
        __syncthreads();
        for (int d = 1; d < 1024; d <<= 1) {
            int t = (tid >= d) ? sh[tid - d] : 0;
            __syncthreads();
            sh[tid] += t;
            __syncthreads();
        }
        if (i < NN) g_rowptr[i] = s_off + sh[tid] - v;  // exclusive
        int tot = sh[1023];
        __syncthreads();
        if (tid == 0) s_off += tot;
        __syncthreads();
    }
    if (tid == 0) g_rowptr[NN] = s_off;  // == EE
}

__global__ void fill_kernel(const void* __restrict__ ei) {
    int e = blockIdx.x * blockDim.x + threadIdx.x;
    if (e < EE) {
        int r = load_ei(ei, e);
        int c = load_ei(ei, (long long)EE + e);
        int p = g_rowptr[c] + atomicAdd(&g_fill[c], 1);
        if (p < EE) {  // defensive (holds when detection is right)
            g_src[p] = r;
            g_w[p]   = g_dinv[r] * g_dinv[c];
        }
    }
}

// ---------------- generic fp32 tiled GEMM: C = A(MxK) @ B(KxNf) ----------------
// BM=64, BN=64, BK=16; 256 threads; 4x4 per-thread tile. Nf,K multiples of 16/64.
__global__ void gemm_kernel(const float* __restrict__ A, const float* __restrict__ B,
                            float* __restrict__ C, int M, int K, int Nf) {
    __shared__ float As[16][68];  // transposed tile, padded
    __shared__ float Bs[16][64];
    int tid = threadIdx.x;
    int tx = tid & 15, ty = tid >> 4;
    int row0 = blockIdx.y * 64, col0 = blockIdx.x * 64;
    float acc[4][4];
#pragma unroll
    for (int i = 0; i < 4; i++)
#pragma unroll
        for (int j = 0; j < 4; j++) acc[i][j] = 0.f;

    for (int k0 = 0; k0 < K; k0 += 16) {
#pragma unroll
        for (int l = tid; l < 1024; l += 256) {
            int r = l >> 4, c = l & 15;
            int gr = row0 + r;
            As[c][r] = (gr < M) ? A[(size_t)gr * K + k0 + c] : 0.f;
        }
#pragma unroll
        for (int l = tid; l < 1024; l += 256) {
            int r = l >> 6, c = l & 63;
            Bs[r][c] = B[(size_t)(k0 + r) * Nf + col0 + c];
        }
        __syncthreads();
#pragma unroll
        for (int kk = 0; kk < 16; kk++) {
            float a[4], b[4];
            *(float4*)a = *(const float4*)&As[kk][ty * 4];
            *(float4*)b = *(const float4*)&Bs[kk][tx * 4];
#pragma unroll
            for (int i = 0; i < 4; i++)
#pragma unroll
                for (int j = 0; j < 4; j++) acc[i][j] += a[i] * b[j];
        }
        __syncthreads();
    }
#pragma unroll
    for (int i = 0; i < 4; i++) {
        int gr = row0 + ty * 4 + i;
        if (gr < M)
            *(float4*)&C[(size_t)gr * Nf + col0 + tx * 4] = *(float4*)acc[i];
    }
}

// ---------------- GCN aggregation (CSR by destination, warp per node) ----------
template <int F, bool RELU, bool WRITE_T>
__global__ void aggregate_kernel(const float* __restrict__ hw,
                                 const float* __restrict__ bias,
                                 float* __restrict__ out,
                                 float* __restrict__ outT) {
    int gw   = (blockIdx.x * blockDim.x + threadIdx.x) >> 5;
    int lane = threadIdx.x & 31;
    if (gw >= NN) return;
    constexpr int R = F / 32;
    float acc[R];
    float d = g_dinv[gw];
    float selfw = d * d;
#pragma unroll
    for (int j = 0; j < R; j++) acc[j] = selfw * hw[(size_t)gw * F + lane + 32 * j];
    int s = g_rowptr[gw], e = g_rowptr[gw + 1];
    for (int p = s; p < e; p++) {
        int r    = g_src[p];
        float ww = g_w[p];
        const float* hr = hw + (size_t)r * F;
#pragma unroll
        for (int j = 0; j < R; j++) acc[j] += ww * hr[lane + 32 * j];
    }
#pragma unroll
    for (int j = 0; j < R; j++) {
        float v = acc[j] + bias[lane + 32 * j];
        if (RELU) v = fmaxf(v, 0.f);
        out[(size_t)gw * F + lane + 32 * j] = v;
        if (WRITE_T) outT[(size_t)(lane + 32 * j) * NN + gw] = v;
    }
}

// ---------------- decoder: out = sigmoid(z @ z^T), 64x128 tiles, f32x2 FMA ----
__global__ void zzt_kernel(float* __restrict__ out) {
    __shared__ float As[64][64];    // As[m][k] = z[row0+m][k]
    __shared__ float Bs[64][128];   // Bs[k][n] = z[col0+n][k] (from zT, coalesced)
    int tid = threadIdx.x;
    int tx = tid & 15, ty = tid >> 4;
    int row0 = blockIdx.y * 64, col0 = blockIdx.x * 128;

#pragma unroll
    for (int l = tid; l < 4096; l += 256) {
        int m = l >> 6, k = l & 63;
        int gr = row0 + m;
        As[m][k] = (gr < NN) ? g_z[(size_t)gr * FOUT + k] : 0.f;
    }
#pragma unroll
    for (int l = tid; l < 8192; l += 256) {
        int k = l >> 7, n = l & 127;
        int gc = col0 + n;
        Bs[k][n] = (gc < NN) ? g_zT[(size_t)k * NN + gc] : 0.f;
    }
    __syncthreads();

    unsigned long long acc2[4][4];
#pragma unroll
    for (int i = 0; i < 4; i++)
#pragma unroll
        for (int j = 0; j < 4; j++) acc2[i][j] = 0ULL;

#pragma unroll
    for (int kk = 0; kk < 64; kk++) {
        float a[4];
#pragma unroll
        for (int i = 0; i < 4; i++) a[i] = As[ty * 4 + i][kk];
        ulonglong2 bA = *(const ulonglong2*)&Bs[kk][tx * 8];
        ulonglong2 bB = *(const ulonglong2*)&Bs[kk][tx * 8 + 4];
        unsigned long long b2[4] = { bA.x, bA.y, bB.x, bB.y };
#pragma unroll
        for (int i = 0; i < 4; i++) {
            unsigned long long ad = pk2(a[i], a[i]);
#pragma unroll
            for (int jj = 0; jj < 4; jj++) ffma2(acc2[i][jj], ad, b2[jj]);
        }
    }

    int gc0 = col0 + tx * 8;
#pragma unroll
    for (int i = 0; i < 4; i++) {
        int gr = row0 + ty * 4 + i;
        if (gr >= NN) continue;
        float v[8];
#pragma unroll
        for (int jj = 0; jj < 4; jj++) {
            float2 f = upk2(acc2[i][jj]);
            v[2 * jj]     = fsig(f.x);
            v[2 * jj + 1] = fsig(f.y);
        }
        float* orow = out + (size_t)gr * NN + gc0;
        if (gc0 + 7 < NN) {
            *(float4*)&orow[0] = make_float4(v[0], v[1], v[2], v[3]);
            *(float4*)&orow[4] = make_float4(v[4], v[5], v[6], v[7]);
        } else {
#pragma unroll
            for (int j = 0; j < 8; j++)
                if (gc0 + j < NN) orow[j] = v[j];
        }
    }
}

// ---------------- launch ----------------
extern "C" void kernel_launch(void* const* d_in, const int* in_sizes, int n_in,
                              void* d_out, int out_size) {
    const float* x   = (const float*)d_in[0];
    const void*  ei  = (const void*)d_in[1];
    const float* W1  = (const float*)d_in[2];
    const float* b1  = (const float*)d_in[3];
    const float* W2  = (const float*)d_in[4];
    const float* b2  = (const float*)d_in[5];
    const float* Wmu = (const float*)d_in[6];
    const float* bmu = (const float*)d_in[7];
    float*       out = (float*)d_out;
    (void)in_sizes; (void)n_in; (void)out_size;

    float *hw, *h, *z, *zT;
    cudaGetSymbolAddress((void**)&hw, g_hw);
    cudaGetSymbolAddress((void**)&h,  g_h);
    cudaGetSymbolAddress((void**)&z,  g_z);
    cudaGetSymbolAddress((void**)&zT, g_zT);

    // graph preprocessing
    detect_kernel<<<1, 1>>>(ei);
    init_kernel<<<(NN + 255) / 256, 256>>>();
    count_kernel<<<(EE + 255) / 256, 256>>>(ei);
    dinv_kernel<<<(NN + 255) / 256, 256>>>();
    scan_kernel<<<1, 1024>>>();
    fill_kernel<<<(EE + 255) / 256, 256>>>(ei);

    const int aggBlocks = (NN * 32 + 255) / 256;

    // layer 1: h = relu(conv(x, W1, b1))
    gemm_kernel<<<dim3(FHID / 64, (NN + 63) / 64), 256>>>(x, W1, hw, NN, FIN, FHID);
    aggregate_kernel<FHID, true, false><<<aggBlocks, 256>>>(hw, b1, h, nullptr);

    // layer 2: h = relu(conv(h, W2, b2))
    gemm_kernel<<<dim3(FHID / 64, (NN + 63) / 64), 256>>>(h, W2, hw, NN, FHID, FHID);
    aggregate_kernel<FHID, true, false><<<aggBlocks, 256>>>(hw, b2, h, nullptr);

    // mu layer (logstd is unused: z = mu in eval)
    gemm_kernel<<<dim3(1, (NN + 63) / 64), 256>>>(h, Wmu, hw, NN, FHID, FOUT);
    aggregate_kernel<FOUT, false, true><<<aggBlocks, 256>>>(hw, bmu, z, zT);

    // decoder: out = sigmoid(z z^T)
    zzt_kernel<<<dim3((NN + 127) / 128, (NN + 63) / 64), 256>>>(out);
}

// round 5
// speedup vs baseline: 2.2301x; 2.2301x over previous
#include <cuda_runtime.h>
#include <cuda_bf16.h>
#include <math.h>
#include <stdint.h>

#define NN 12000
#define EE 384000
#define FIN 512
#define FHID 256
#define FOUT 64

// ---------------- scratch (static __device__, no allocs) ----------------
__device__ int   g_is64;
__device__ float g_deg[NN];
__device__ float g_dinv[NN];
__device__ int   g_rowptr[NN + 1];
__device__ int   g_fill[NN];
__device__ int   g_src[EE];
__device__ float g_w[EE];
__device__ float g_hw[NN * FHID];   // linear output (pre-aggregation)
__device__ float g_h[NN * FHID];    // conv output
__device__ float g_z[NN * FOUT];    // mu
// split-bf16 operand buffers (reused across layers; sized for the largest)
__device__ __nv_bfloat16 g_ah[NN * FIN], g_al[NN * FIN];
__device__ __nv_bfloat16 g_bh[FHID * FIN], g_bl[FHID * FIN];

// ---------------- helpers ----------------
__device__ __forceinline__ float fsig(float s) {
    return __fdividef(1.0f, 1.0f + __expf(-s));
}
__device__ __forceinline__ uint32_t smem_u32(const void* p) {
    uint32_t a;
    asm("{ .reg .u64 t; cvta.to.shared.u64 t, %1; cvt.u32.u64 %0, t; }" : "=r"(a) : "l"(p));
    return a;
}
__device__ __forceinline__ void ldsm4(uint32_t addr, uint32_t& r0, uint32_t& r1,
                                      uint32_t& r2, uint32_t& r3) {
    asm volatile("ldmatrix.sync.aligned.m8n8.x4.shared.b16 {%0,%1,%2,%3}, [%4];"
                 : "=r"(r0), "=r"(r1), "=r"(r2), "=r"(r3) : "r"(addr));
}
__device__ __forceinline__ void mma16816(float* c, const uint32_t* a,
                                         uint32_t b0, uint32_t b1) {
    asm volatile(
        "mma.sync.aligned.m16n8k16.row.col.f32.bf16.bf16.f32 "
        "{%0,%1,%2,%3}, {%4,%5,%6,%7}, {%8,%9}, {%0,%1,%2,%3};"
        : "+f"(c[0]), "+f"(c[1]), "+f"(c[2]), "+f"(c[3])
        : "r"(a[0]), "r"(a[1]), "r"(a[2]), "r"(a[3]), "r"(b0), "r"(b1));
}

// Load edge index element honoring detected dtype, clamped to [0, NN).
__device__ __forceinline__ int load_ei(const void* ei, long long idx) {
    int v;
    if (g_is64) v = (int)((const long long*)ei)[idx];
    else        v = ((const int*)ei)[idx];
    return min(max(v, 0), NN - 1);
}

// ---------------- dtype detection + preprocessing ----------------
__global__ void detect_kernel(const void* ei) {
    const int* w = (const int*)ei;
    bool is64 = true;
    for (int i = 1; i < 64; i += 2)
        if (w[i] != 0) { is64 = false; break; }
    g_is64 = is64 ? 1 : 0;
}

__global__ void init_kernel() {
    int i = blockIdx.x * blockDim.x + threadIdx.x;
    if (i < NN) { g_deg[i] = 1.0f; g_fill[i] = 0; }
}

__global__ void count_kernel(const void* __restrict__ ei) {
    int e = blockIdx.x * blockDim.x + threadIdx.x;
    if (e < EE) atomicAdd(&g_deg[load_ei(ei, (long long)EE + e)], 1.0f);
}

__global__ void dinv_kernel() {
    int i = blockIdx.x * blockDim.x + threadIdx.x;
    if (i < NN) g_dinv[i] = rsqrtf(g_deg[i]);
}

__global__ void scan_kernel() {
    __shared__ int sh[1024];
    __shared__ int s_off;
    int tid = threadIdx.x;
    if (tid == 0) s_off = 0;
    __syncthreads();
    for (int base = 0; base < NN; base += 1024) {
        int i = base + tid;
        int v = (i < NN) ? ((int)(g_deg[i] + 0.5f) - 1) : 0;
        sh[tid] = v;
        __syncthreads();
        for (int d = 1; d < 1024; d <<= 1) {
            int t = (tid >= d) ? sh[tid - d] : 0;
            __syncthreads();
            sh[tid] += t;
            __syncthreads();
        }
        if (i < NN) g_rowptr[i] = s_off + sh[tid] - v;
        int tot = sh[1023];
        __syncthreads();
        if (tid == 0) s_off += tot;
        __syncthreads();
    }
    if (tid == 0) g_rowptr[NN] = s_off;
}

__global__ void fill_kernel(const void* __restrict__ ei) {
    int e = blockIdx.x * blockDim.x + threadIdx.x;
    if (e < EE) {
        int r = load_ei(ei, e);
        int c = load_ei(ei, (long long)EE + e);
        int p = g_rowptr[c] + atomicAdd(&g_fill[c], 1);
        if (p < EE) {
            g_src[p] = r;
            g_w[p]   = g_dinv[r] * g_dinv[c];
        }
    }
}

// ---------------- fp32 -> bf16 hi/lo split ----------------
__global__ void split_kernel(const float* __restrict__ src,
                             __nv_bfloat16* __restrict__ dh,
                             __nv_bfloat16* __restrict__ dl, int n) {
    int i = blockIdx.x * blockDim.x + threadIdx.x;
    if (i < n) {
        float v = src[i];
        __nv_bfloat16 h = __float2bfloat16(v);
        dh[i] = h;
        dl[i] = __float2bfloat16(v - __bfloat162float(h));
    }
}

// W [K][N] row-major -> Wt hi/lo [N][K]
__global__ void splitT_kernel(const float* __restrict__ W,
                              __nv_bfloat16* __restrict__ th,
                              __nv_bfloat16* __restrict__ tl, int K, int N) {
    int i = blockIdx.x * blockDim.x + threadIdx.x;
    if (i < K * N) {
        int k = i / N, n = i % N;
        float v = W[i];
        __nv_bfloat16 h = __float2bfloat16(v);
        th[n * K + k] = h;
        tl[n * K + k] = __float2bfloat16(v - __bfloat162float(h));
    }
}

// ---------------- split-bf16 tensor-core GEMM: C = A(M,K) . B(N,K)^T ----------
// 3 passes: Ah*Bh + Ah*Bl + Al*Bh. CTA tile 128x128, warp tile 32x64, KC=64.
#define SA 72                       // smem row stride in bf16 (144 B)
#define MMA_SMEM (4 * 128 * SA * 2) // 73728 B

template <bool SIG>
__global__ void __launch_bounds__(256, 2) mma_gemm_kernel(
    const __nv_bfloat16* __restrict__ Ah_, const __nv_bfloat16* __restrict__ Al_,
    const __nv_bfloat16* __restrict__ Bh_, const __nv_bfloat16* __restrict__ Bl_,
    float* __restrict__ C, int M, int N, int K) {
    extern __shared__ __nv_bfloat16 sm[];
    uint32_t sb   = smem_u32(sm);
    uint32_t sAh  = sb;
    uint32_t sAl  = sb + 128 * SA * 2;
    uint32_t sBh  = sb + 2 * 128 * SA * 2;
    uint32_t sBl  = sb + 3 * 128 * SA * 2;
    __nv_bfloat16* pAh = sm;
    __nv_bfloat16* pAl = sm + 128 * SA;
    __nv_bfloat16* pBh = sm + 2 * 128 * SA;
    __nv_bfloat16* pBl = sm + 3 * 128 * SA;

    int tid = threadIdx.x, wid = tid >> 5, lane = tid & 31;
    int row0 = blockIdx.y * 128, col0 = blockIdx.x * 128;
    int wm = wid & 3, wn = wid >> 2;   // warp grid 4(M) x 2(N)

    float c[2][8][4];
#pragma unroll
    for (int a = 0; a < 2; a++)
#pragma unroll
        for (int b = 0; b < 8; b++)
#pragma unroll
            for (int d = 0; d < 4; d++) c[a][b][d] = 0.f;

    const uint4 z4 = make_uint4(0, 0, 0, 0);
    for (int k0 = 0; k0 < K; k0 += 64) {
        // stage 128x64 hi/lo tiles for A and B (16B per thread-iter, coalesced)
#pragma unroll
        for (int it = 0; it < 4; it++) {
            int v = it * 256 + tid;          // 0..1023
            int r = v >> 3, cs = (v & 7) * 8;
            int gr = row0 + r;
            size_t ga = (size_t)gr * K + k0 + cs;
            uint4 t;
            t = (gr < M) ? *(const uint4*)(Ah_ + ga) : z4;
            *(uint4*)(pAh + r * SA + cs) = t;
            t = (gr < M) ? *(const uint4*)(Al_ + ga) : z4;
            *(uint4*)(pAl + r * SA + cs) = t;
            int gc = col0 + r;
            size_t gb = (size_t)gc * K + k0 + cs;
            t = (gc < N) ? *(const uint4*)(Bh_ + gb) : z4;
            *(uint4*)(pBh + r * SA + cs) = t;
            t = (gc < N) ? *(const uint4*)(Bl_ + gb) : z4;
            *(uint4*)(pBl + r * SA + cs) = t;
        }
        __syncthreads();

        int quad = lane >> 3, qr = lane & 7;
        int mq = (quad & 1) * 8 + qr;   // row offset within 16
        int kq = (quad >> 1) * 8;       // col offset within 16

#pragma unroll
        for (int ks = 0; ks < 64; ks += 16) {
            uint32_t aH[2][4], aL[2][4];
#pragma unroll
            for (int mt = 0; mt < 2; mt++) {
                uint32_t off = (uint32_t)((wm * 32 + mt * 16 + mq) * SA + ks + kq) * 2;
                ldsm4(sAh + off, aH[mt][0], aH[mt][1], aH[mt][2], aH[mt][3]);
                ldsm4(sAl + off, aL[mt][0], aL[mt][1], aL[mt][2], aL[mt][3]);
            }
#pragma unroll
            for (int np = 0; np < 4; np++) {
                uint32_t off = (uint32_t)((wn * 64 + np * 16 + mq) * SA + ks + kq) * 2;
                uint32_t bh[4], bl[4];
                ldsm4(sBh + off, bh[0], bh[1], bh[2], bh[3]);
                ldsm4(sBl + off, bl[0], bl[1], bl[2], bl[3]);
#pragma unroll
                for (int mt = 0; mt < 2; mt++) {
                    float* c0 = c[mt][np * 2];
                    float* c1 = c[mt][np * 2 + 1];
                    mma16816(c0, aH[mt], bh[0], bh[2]);
                    mma16816(c0, aH[mt], bl[0], bl[2]);
                    mma16816(c0, aL[mt], bh[0], bh[2]);
                    mma16816(c1, aH[mt], bh[1], bh[3]);
                    mma16816(c1, aH[mt], bl[1], bl[3]);
                    mma16816(c1, aL[mt], bh[1], bh[3]);
                }
            }
        }
        __syncthreads();
    }

    // epilogue
    int mb = row0 + wm * 32 + (lane >> 2);
    int nb = col0 + wn * 64 + (lane & 3) * 2;
#pragma unroll
    for (int mt = 0; mt < 2; mt++) {
#pragma unroll
        for (int nt = 0; nt < 8; nt++) {
            int gr = mb + mt * 16;
            int gc = nb + nt * 8;
            if (gc < N) {
                float v0 = c[mt][nt][0], v1 = c[mt][nt][1];
                float v2 = c[mt][nt][2], v3 = c[mt][nt][3];
                if (SIG) { v0 = fsig(v0); v1 = fsig(v1); v2 = fsig(v2); v3 = fsig(v3); }
                if (gr < M)     *(float2*)(C + (size_t)gr * N + gc)       = make_float2(v0, v1);
                if (gr + 8 < M) *(float2*)(C + (size_t)(gr + 8) * N + gc) = make_float2(v2, v3);
            }
        }
    }
}

// ---------------- GCN aggregation (CSR by destination, warp per node) ----------
template <int F, bool RELU>
__global__ void aggregate_kernel(const float* __restrict__ hw,
                                 const float* __restrict__ bias,
                                 float* __restrict__ out) {
    int gw   = (blockIdx.x * blockDim.x + threadIdx.x) >> 5;
    int lane = threadIdx.x & 31;
    if (gw >= NN) return;
    constexpr int R = F / 32;
    float acc[R];
    float d = g_dinv[gw];
    float selfw = d * d;
#pragma unroll
    for (int j = 0; j < R; j++) acc[j] = selfw * hw[(size_t)gw * F + lane + 32 * j];
    int s = g_rowptr[gw], e = g_rowptr[gw + 1];
    for (int p = s; p < e; p++) {
        int r    = g_src[p];
        float ww = g_w[p];
        const float* hr = hw + (size_t)r * F;
#pragma unroll
        for (int j = 0; j < R; j++) acc[j] += ww * hr[lane + 32 * j];
    }
#pragma unroll
    for (int j = 0; j < R; j++) {
        float v = acc[j] + bias[lane + 32 * j];
        if (RELU) v = fmaxf(v, 0.f);
        out[(size_t)gw * F + lane + 32 * j] = v;
    }
}

// ---------------- launch ----------------
extern "C" void kernel_launch(void* const* d_in, const int* in_sizes, int n_in,
                              void* d_out, int out_size) {
    const float* x   = (const float*)d_in[0];
    const void*  ei  = (const void*)d_in[1];
    const float* W1  = (const float*)d_in[2];
    const float* b1  = (const float*)d_in[3];
    const float* W2  = (const float*)d_in[4];
    const float* b2  = (const float*)d_in[5];
    const float* Wmu = (const float*)d_in[6];
    const float* bmu = (const float*)d_in[7];
    float*       out = (float*)d_out;
    (void)in_sizes; (void)n_in; (void)out_size;

    float *hw, *h, *z;
    __nv_bfloat16 *ah, *al, *bh, *bl;
    cudaGetSymbolAddress((void**)&hw, g_hw);
    cudaGetSymbolAddress((void**)&h,  g_h);
    cudaGetSymbolAddress((void**)&z,  g_z);
    cudaGetSymbolAddress((void**)&ah, g_ah);
    cudaGetSymbolAddress((void**)&al, g_al);
    cudaGetSymbolAddress((void**)&bh, g_bh);
    cudaGetSymbolAddress((void**)&bl, g_bl);

    cudaFuncSetAttribute(mma_gemm_kernel<false>,
                         cudaFuncAttributeMaxDynamicSharedMemorySize, MMA_SMEM);
    cudaFuncSetAttribute(mma_gemm_kernel<true>,
                         cudaFuncAttributeMaxDynamicSharedMemorySize, MMA_SMEM);

    // graph preprocessing
    detect_kernel<<<1, 1>>>(ei);
    init_kernel<<<(NN + 255) / 256, 256>>>();
    count_kernel<<<(EE + 255) / 256, 256>>>(ei);
    dinv_kernel<<<(NN + 255) / 256, 256>>>();
    scan_kernel<<<1, 1024>>>();
    fill_kernel<<<(EE + 255) / 256, 256>>>(ei);

    const int aggBlocks = (NN * 32 + 255) / 256;
    const int mTiles = (NN + 127) / 128;  // 94

    // layer 1
    split_kernel<<<(NN * FIN + 255) / 256, 256>>>(x, ah, al, NN * FIN);
    splitT_kernel<<<(FIN * FHID + 255) / 256, 256>>>(W1, bh, bl, FIN, FHID);
    mma_gemm_kernel<false><<<dim3(FHID / 128, mTiles), 256, MMA_SMEM>>>(
        ah, al, bh, bl, hw, NN, FHID, FIN);
    aggregate_kernel<FHID, true><<<aggBlocks, 256>>>(hw, b1, h);

    // layer 2
    split_kernel<<<(NN * FHID + 255) / 256, 256>>>(h, ah, al, NN * FHID);
    splitT_kernel<<<(FHID * FHID + 255) / 256, 256>>>(W2, bh, bl, FHID, FHID);
    mma_gemm_kernel<false><<<dim3(FHID / 128, mTiles), 256, MMA_SMEM>>>(
        ah, al, bh, bl, hw, NN, FHID, FHID);
    aggregate_kernel<FHID, true><<<aggBlocks, 256>>>(hw, b2, h);

    // mu layer (logstd unused: z = mu in eval)
    split_kernel<<<(NN * FHID + 255) / 256, 256>>>(h, ah, al, NN * FHID);
    splitT_kernel<<<(FHID * FOUT + 255) / 256, 256>>>(Wmu, bh, bl, FHID, FOUT);
    mma_gemm_kernel<false><<<dim3(1, mTiles), 256, MMA_SMEM>>>(
        ah, al, bh, bl, hw, NN, FOUT, FHID);
    aggregate_kernel<FOUT, false><<<aggBlocks, 256>>>(hw, bmu, z);

    // decoder: out = sigmoid(z z^T)
    split_kernel<<<(NN * FOUT + 255) / 256, 256>>>(z, ah, al, NN * FOUT);
    mma_gemm_kernel<true><<<dim3(mTiles, mTiles), 256, MMA_SMEM>>>(
        ah, al, ah, al, out, NN, NN, FOUT);
}

// round 6
// speedup vs baseline: 2.9587x; 1.3267x over previous
#include <cuda_runtime.h>
#include <cuda_bf16.h>
#include <math.h>
#include <stdint.h>

#define NN 12000
#define EE 384000
#define FIN 512
#define FHID 256
#define FOUT 64

// ---------------- scratch (static __device__, no allocs) ----------------
__device__ int   g_is64;
__device__ int   g_cursor;
__device__ float g_deg[NN];
__device__ float g_dinv[NN];
__device__ int   g_rs[NN];          // CSR segment start (unordered layout)
__device__ int   g_fill[NN];
__device__ int   g_src[EE];
__device__ float g_w[EE];
__device__ float g_hw[NN * FHID];   // linear output (pre-aggregation)
// split-bf16 operand buffers (reused across layers; sized for the largest)
__device__ __nv_bfloat16 g_ah[NN * FIN], g_al[NN * FIN];
__device__ __nv_bfloat16 g_bh[FHID * FIN], g_bl[FHID * FIN];

// ---------------- helpers ----------------
__device__ __forceinline__ float fsig(float s) {
    return __fdividef(1.0f, 1.0f + __expf(-s));
}
__device__ __forceinline__ uint32_t smem_u32(const void* p) {
    uint32_t a;
    asm("{ .reg .u64 t; cvta.to.shared.u64 t, %1; cvt.u32.u64 %0, t; }" : "=r"(a) : "l"(p));
    return a;
}
__device__ __forceinline__ void ldsm4(uint32_t addr, uint32_t& r0, uint32_t& r1,
                                      uint32_t& r2, uint32_t& r3) {
    asm volatile("ldmatrix.sync.aligned.m8n8.x4.shared.b16 {%0,%1,%2,%3}, [%4];"
                 : "=r"(r0), "=r"(r1), "=r"(r2), "=r"(r3) : "r"(addr));
}
__device__ __forceinline__ void mma16816(float* c, const uint32_t* a,
                                         uint32_t b0, uint32_t b1) {
    asm volatile(
        "mma.sync.aligned.m16n8k16.row.col.f32.bf16.bf16.f32 "
        "{%0,%1,%2,%3}, {%4,%5,%6,%7}, {%8,%9}, {%0,%1,%2,%3};"
        : "+f"(c[0]), "+f"(c[1]), "+f"(c[2]), "+f"(c[3])
        : "r"(a[0]), "r"(a[1]), "r"(a[2]), "r"(a[3]), "r"(b0), "r"(b1));
}

// Load edge index element honoring detected dtype, clamped to [0, NN).
__device__ __forceinline__ int load_ei(const void* ei, long long idx) {
    int v;
    if (g_is64) v = (int)((const long long*)ei)[idx];
    else        v = ((const int*)ei)[idx];
    return min(max(v, 0), NN - 1);
}

// ---------------- dtype detection + preprocessing ----------------
__global__ void detect_kernel(const void* ei) {
    const int* w = (const int*)ei;
    bool is64 = true;
    for (int i = 1; i < 64; i += 2)
        if (w[i] != 0) { is64 = false; break; }
    g_is64 = is64 ? 1 : 0;
}

__global__ void init_kernel() {
    int i = blockIdx.x * blockDim.x + threadIdx.x;
    if (i < NN) { g_deg[i] = 1.0f; g_fill[i] = 0; }
    if (i == 0) g_cursor = 0;
}

__global__ void count_kernel(const void* __restrict__ ei) {
    int e = blockIdx.x * blockDim.x + threadIdx.x;
    if (e < EE) atomicAdd(&g_deg[load_ei(ei, (long long)EE + e)], 1.0f);
}

__global__ void dinv_kernel() {
    int i = blockIdx.x * blockDim.x + threadIdx.x;
    if (i < NN) g_dinv[i] = rsqrtf(g_deg[i]);
}

// unordered CSR layout: each node grabs a contiguous region via atomic cursor
__global__ void offsets_kernel() {
    int i = blockIdx.x * blockDim.x + threadIdx.x;
    if (i < NN) {
        int d = (int)(g_deg[i] + 0.5f) - 1;   // in-degree (minus self loop)
        g_rs[i] = atomicAdd(&g_cursor, d);
    }
}

__global__ void fill_kernel(const void* __restrict__ ei) {
    int e = blockIdx.x * blockDim.x + threadIdx.x;
    if (e < EE) {
        int r = load_ei(ei, e);
        int c = load_ei(ei, (long long)EE + e);
        int p = g_rs[c] + atomicAdd(&g_fill[c], 1);
        if (p < EE) {
            g_src[p] = r;
            g_w[p]   = g_dinv[r] * g_dinv[c];
        }
    }
}

// ---------------- fp32 -> bf16 hi/lo split (x only) ----------------
__global__ void split_kernel(const float* __restrict__ src,
                             __nv_bfloat16* __restrict__ dh,
                             __nv_bfloat16* __restrict__ dl, int n) {
    int i = blockIdx.x * blockDim.x + threadIdx.x;
    if (i < n) {
        float v = src[i];
        __nv_bfloat16 h = __float2bfloat16(v);
        dh[i] = h;
        dl[i] = __float2bfloat16(v - __bfloat162float(h));
    }
}

// W [K][N] row-major -> Wt hi/lo [N][K]
__global__ void splitT_kernel(const float* __restrict__ W,
                              __nv_bfloat16* __restrict__ th,
                              __nv_bfloat16* __restrict__ tl, int K, int N) {
    int i = blockIdx.x * blockDim.x + threadIdx.x;
    if (i < K * N) {
        int k = i / N, n = i % N;
        float v = W[i];
        __nv_bfloat16 h = __float2bfloat16(v);
        th[n * K + k] = h;
        tl[n * K + k] = __float2bfloat16(v - __bfloat162float(h));
    }
}

// ---------------- split-bf16 tensor-core GEMM: C = A(M,K) . B(N,K)^T ----------
#define SA 72                       // smem row stride in bf16 (144 B)
#define MMA_SMEM (4 * 128 * SA * 2) // 73728 B

template <bool SIG>
__device__ __forceinline__ void mma_tile_body(
    const __nv_bfloat16* Ah_, const __nv_bfloat16* Al_,
    const __nv_bfloat16* Bh_, const __nv_bfloat16* Bl_,
    int M, int N, int K, int row0, int col0,
    __nv_bfloat16* sm, float c[2][8][4]) {
    uint32_t sb  = smem_u32(sm);
    uint32_t sAh = sb;
    uint32_t sAl = sb + 128 * SA * 2;
    uint32_t sBh = sb + 2 * 128 * SA * 2;
    uint32_t sBl = sb + 3 * 128 * SA * 2;
    __nv_bfloat16* pAh = sm;
    __nv_bfloat16* pAl = sm + 128 * SA;
    __nv_bfloat16* pBh = sm + 2 * 128 * SA;
    __nv_bfloat16* pBl = sm + 3 * 128 * SA;

    int tid = threadIdx.x, wid = tid >> 5, lane = tid & 31;
    int wm = wid & 3, wn = wid >> 2;

#pragma unroll
    for (int a = 0; a < 2; a++)
#pragma unroll
        for (int b = 0; b < 8; b++)
#pragma unroll
            for (int d = 0; d < 4; d++) c[a][b][d] = 0.f;

    const uint4 z4 = make_uint4(0, 0, 0, 0);
    for (int k0 = 0; k0 < K; k0 += 64) {
#pragma unroll
        for (int it = 0; it < 4; it++) {
            int v = it * 256 + tid;
            int r = v >> 3, cs = (v & 7) * 8;
            int gr = row0 + r;
            size_t ga = (size_t)gr * K + k0 + cs;
            uint4 t;
            t = (gr < M) ? *(const uint4*)(Ah_ + ga) : z4;
            *(uint4*)(pAh + r * SA + cs) = t;
            t = (gr < M) ? *(const uint4*)(Al_ + ga) : z4;
            *(uint4*)(pAl + r * SA + cs) = t;
            int gc = col0 + r;
            size_t gb = (size_t)gc * K + k0 + cs;
            t = (gc < N) ? *(const uint4*)(Bh_ + gb) : z4;
            *(uint4*)(pBh + r * SA + cs) = t;
            t = (gc < N) ? *(const uint4*)(Bl_ + gb) : z4;
            *(uint4*)(pBl + r * SA + cs) = t;
        }
        __syncthreads();

        int quad = lane >> 3, qr = lane & 7;
        int mq = (quad & 1) * 8 + qr;
        int kq = (quad >> 1) * 8;

#pragma unroll
        for (int ks = 0; ks < 64; ks += 16) {
            uint32_t aH[2][4], aL[2][4];
#pragma unroll
            for (int mt = 0; mt < 2; mt++) {
                uint32_t off = (uint32_t)((wm * 32 + mt * 16 + mq) * SA + ks + kq) * 2;
                ldsm4(sAh + off, aH[mt][0], aH[mt][1], aH[mt][2], aH[mt][3]);
                ldsm4(sAl + off, aL[mt][0], aL[mt][1], aL[mt][2], aL[mt][3]);
            }
#pragma unroll
            for (int np = 0; np < 4; np++) {
                uint32_t off = (uint32_t)((wn * 64 + np * 16 + mq) * SA + ks + kq) * 2;
                uint32_t bh[4], bl[4];
                ldsm4(sBh + off, bh[0], bh[1], bh[2], bh[3]);
                ldsm4(sBl + off, bl[0], bl[1], bl[2], bl[3]);
#pragma unroll
                for (int mt = 0; mt < 2; mt++) {
                    float* c0 = c[mt][np * 2];
                    float* c1 = c[mt][np * 2 + 1];
                    mma16816(c0, aH[mt], bh[0], bh[2]);
                    mma16816(c0, aH[mt], bl[0], bl[2]);
                    mma16816(c0, aL[mt], bh[0], bh[2]);
                    mma16816(c1, aH[mt], bh[1], bh[3]);
                    mma16816(c1, aH[mt], bl[1], bl[3]);
                    mma16816(c1, aL[mt], bh[1], bh[3]);
                }
            }
        }
        __syncthreads();
    }
    if (SIG) {
#pragma unroll
        for (int a = 0; a < 2; a++)
#pragma unroll
            for (int b = 0; b < 8; b++)
#pragma unroll
                for (int d = 0; d < 4; d++) c[a][b][d] = fsig(c[a][b][d]);
    }
}

// plain GEMM (feature layers)
__global__ void __launch_bounds__(256, 2) mma_gemm_kernel(
    const __nv_bfloat16* __restrict__ Ah_, const __nv_bfloat16* __restrict__ Al_,
    const __nv_bfloat16* __restrict__ Bh_, const __nv_bfloat16* __restrict__ Bl_,
    float* __restrict__ C, int M, int N, int K) {
    extern __shared__ __nv_bfloat16 sm[];
    int row0 = blockIdx.y * 128, col0 = blockIdx.x * 128;
    float c[2][8][4];
    mma_tile_body<false>(Ah_, Al_, Bh_, Bl_, M, N, K, row0, col0, sm, c);

    int tid = threadIdx.x, wid = tid >> 5, lane = tid & 31;
    int wm = wid & 3, wn = wid >> 2;
    int mb = row0 + wm * 32 + (lane >> 2);
    int nb = col0 + wn * 64 + (lane & 3) * 2;
#pragma unroll
    for (int mt = 0; mt < 2; mt++) {
#pragma unroll
        for (int nt = 0; nt < 8; nt++) {
            int gr = mb + mt * 16;
            int gc = nb + nt * 8;
            if (gc < N) {
                if (gr < M)     *(float2*)(C + (size_t)gr * N + gc)       = make_float2(c[mt][nt][0], c[mt][nt][1]);
                if (gr + 8 < M) *(float2*)(C + (size_t)(gr + 8) * N + gc) = make_float2(c[mt][nt][2], c[mt][nt][3]);
            }
        }
    }
}

// symmetric decoder: out = sigmoid(z z^T); lower-triangle tiles, mirrored store
__global__ void __launch_bounds__(256, 2) zzt_sym_kernel(
    const __nv_bfloat16* __restrict__ zh, const __nv_bfloat16* __restrict__ zl,
    float* __restrict__ out) {
    extern __shared__ __nv_bfloat16 sm[];
    // linear block index -> lower-triangle tile (by >= bx)
    int i = blockIdx.x;
    int by = (int)((sqrtf(8.0f * (float)i + 1.0f) - 1.0f) * 0.5f);
    while ((by + 1) * (by + 2) / 2 <= i) by++;
    while (by * (by + 1) / 2 > i) by--;
    int bx = i - by * (by + 1) / 2;
    int row0 = by * 128, col0 = bx * 128;

    float c[2][8][4];
    mma_tile_body<true>(zh, zl, zh, zl, NN, NN, FOUT, row0, col0, sm, c);

    int tid = threadIdx.x, wid = tid >> 5, lane = tid & 31;
    int wm = wid & 3, wn = wid >> 2;
    int mb = row0 + wm * 32 + (lane >> 2);
    int nb = col0 + wn * 64 + (lane & 3) * 2;

    // direct store of tile (by, bx)
#pragma unroll
    for (int mt = 0; mt < 2; mt++) {
#pragma unroll
        for (int nt = 0; nt < 8; nt++) {
            int gr = mb + mt * 16;
            int gc = nb + nt * 8;
            if (gc < NN) {
                if (gr < NN)     *(float2*)(out + (size_t)gr * NN + gc)       = make_float2(c[mt][nt][0], c[mt][nt][1]);
                if (gr + 8 < NN) *(float2*)(out + (size_t)(gr + 8) * NN + gc) = make_float2(c[mt][nt][2], c[mt][nt][3]);
            }
        }
    }

    if (bx == by) return;

    // mirrored tile (bx, by): transpose through smem stage, coalesced STG
    float* stage = reinterpret_cast<float*>(sm);   // 128 x 132 fp32 = 67584 B
    __syncthreads();                                // operand tiles dead; reuse
    int rl0 = wm * 32 + (lane >> 2);
    int cl0 = wn * 64 + (lane & 3) * 2;
#pragma unroll
    for (int mt = 0; mt < 2; mt++) {
#pragma unroll
        for (int nt = 0; nt < 8; nt++) {
            int rl = rl0 + mt * 16;
            int cl = cl0 + nt * 8;
            stage[cl * 132 + rl]           = c[mt][nt][0];
            stage[(cl + 1) * 132 + rl]     = c[mt][nt][1];
            stage[cl * 132 + rl + 8]       = c[mt][nt][2];
            stage[(cl + 1) * 132 + rl + 8] = c[mt][nt][3];
        }
    }
    __syncthreads();
#pragma unroll
    for (int it = 0; it < 16; it++) {
        int idx = it * 256 + tid;
        int rr = idx >> 5;            // mirror row within tile
        int cc = (idx & 31) * 4;      // mirror col within tile
        int gr = col0 + rr;           // < NN guaranteed (bx < by)
        int gc = row0 + cc;
        float4 v = *(float4*)&stage[rr * 132 + cc];
        float* p = out + (size_t)gr * NN + gc;
        if (gc + 3 < NN) *(float4*)p = v;
        else {
            if (gc < NN)     p[0] = v.x;
            if (gc + 1 < NN) p[1] = v.y;
            if (gc + 2 < NN) p[2] = v.z;
            if (gc + 3 < NN) p[3] = v.w;
        }
    }
}

// ---------------- GCN aggregation (CSR by destination, warp per node) ----------
// fp32 accumulate, writes bf16 hi/lo split directly
template <int F, bool RELU>
__global__ void aggregate_bf16_kernel(const float* __restrict__ hw,
                                      const float* __restrict__ bias,
                                      __nv_bfloat16* __restrict__ oh,
                                      __nv_bfloat16* __restrict__ ol) {
    int gw   = (blockIdx.x * blockDim.x + threadIdx.x) >> 5;
    int lane = threadIdx.x & 31;
    if (gw >= NN) return;
    constexpr int R = F / 32;
    float acc[R];
    float d = g_dinv[gw];
    float selfw = d * d;
#pragma unroll
    for (int j = 0; j < R; j++) acc[j] = selfw * hw[(size_t)gw * F + lane + 32 * j];
    int s = g_rs[gw];
    int e = s + ((int)(g_deg[gw] + 0.5f) - 1);
    for (int p = s; p < e; p++) {
        int r    = g_src[p];
        float ww = g_w[p];
        const float* hr = hw + (size_t)r * F;
#pragma unroll
        for (int j = 0; j < R; j++) acc[j] += ww * hr[lane + 32 * j];
    }
#pragma unroll
    for (int j = 0; j < R; j++) {
        float v = acc[j] + bias[lane + 32 * j];
        if (RELU) v = fmaxf(v, 0.f);
        __nv_bfloat16 h = __float2bfloat16(v);
        oh[(size_t)gw * F + lane + 32 * j] = h;
        ol[(size_t)gw * F + lane + 32 * j] = __float2bfloat16(v - __bfloat162float(h));
    }
}

// ---------------- launch ----------------
extern "C" void kernel_launch(void* const* d_in, const int* in_sizes, int n_in,
                              void* d_out, int out_size) {
    const float* x   = (const float*)d_in[0];
    const void*  ei  = (const void*)d_in[1];
    const float* W1  = (const float*)d_in[2];
    const float* b1  = (const float*)d_in[3];
    const float* W2  = (const float*)d_in[4];
    const float* b2  = (const float*)d_in[5];
    const float* Wmu = (const float*)d_in[6];
    const float* bmu = (const float*)d_in[7];
    float*       out = (float*)d_out;
    (void)in_sizes; (void)n_in; (void)out_size;

    float* hw;
    __nv_bfloat16 *ah, *al, *bh, *bl;
    cudaGetSymbolAddress((void**)&hw, g_hw);
    cudaGetSymbolAddress((void**)&ah, g_ah);
    cudaGetSymbolAddress((void**)&al, g_al);
    cudaGetSymbolAddress((void**)&bh, g_bh);
    cudaGetSymbolAddress((void**)&bl, g_bl);

    cudaFuncSetAttribute(mma_gemm_kernel,
                         cudaFuncAttributeMaxDynamicSharedMemorySize, MMA_SMEM);
    cudaFuncSetAttribute(zzt_sym_kernel,
                         cudaFuncAttributeMaxDynamicSharedMemorySize, MMA_SMEM);

    // graph preprocessing
    detect_kernel<<<1, 1>>>(ei);
    init_kernel<<<(NN + 255) / 256, 256>>>();
    count_kernel<<<(EE + 255) / 256, 256>>>(ei);
    dinv_kernel<<<(NN + 255) / 256, 256>>>();
    offsets_kernel<<<(NN + 255) / 256, 256>>>();
    fill_kernel<<<(EE + 255) / 256, 256>>>(ei);

    const int aggBlocks = (NN * 32 + 255) / 256;
    const int mTiles = (NN + 127) / 128;  // 94

    // layer 1
    split_kernel<<<(NN * FIN + 255) / 256, 256>>>(x, ah, al, NN * FIN);
    splitT_kernel<<<(FIN * FHID + 255) / 256, 256>>>(W1, bh, bl, FIN, FHID);
    mma_gemm_kernel<<<dim3(FHID / 128, mTiles), 256, MMA_SMEM>>>(
        ah, al, bh, bl, hw, NN, FHID, FIN);
    aggregate_bf16_kernel<FHID, true><<<aggBlocks, 256>>>(hw, b1, ah, al);

    // layer 2
    splitT_kernel<<<(FHID * FHID + 255) / 256, 256>>>(W2, bh, bl, FHID, FHID);
    mma_gemm_kernel<<<dim3(FHID / 128, mTiles), 256, MMA_SMEM>>>(
        ah, al, bh, bl, hw, NN, FHID, FHID);
    aggregate_bf16_kernel<FHID, true><<<aggBlocks, 256>>>(hw, b2, ah, al);

    // mu layer (logstd unused: z = mu in eval)
    splitT_kernel<<<(FHID * FOUT + 255) / 256, 256>>>(Wmu, bh, bl, FHID, FOUT);
    mma_gemm_kernel<<<dim3(1, mTiles), 256, MMA_SMEM>>>(
        ah, al, bh, bl, hw, NN, FOUT, FHID);
    aggregate_bf16_kernel<FOUT, false><<<aggBlocks, 256>>>(hw, bmu, ah, al);

    // decoder: out = sigmoid(z z^T), symmetric lower-triangle + mirror
    const int triTiles = mTiles * (mTiles + 1) / 2;  // 4465
    zzt_sym_kernel<<<triTiles, 256, MMA_SMEM>>>(ah, al, out);
}